// round 1
// baseline (speedup 1.0000x reference)
#include <cuda_runtime.h>
#include <cuda_bf16.h>
#include <cstdint>

// Problem constants (fixed by the reference).
#define BATCH 64
#define SEQ   512
#define DIM   1024
#define TAGS  32

// Scratch: emissions x = feat @ W + b  (fp32, 4 MB) and per-batch llh.
__device__ float g_x[BATCH * SEQ * TAGS];
__device__ float g_llh[BATCH];

// ---------------------------------------------------------------------------
// Kernel 1: emissions GEMM.  x[32768,32] = feat[32768,1024] @ W[1024,32] + b
// bf16 mma.sync m16n8k16, fp32 accumulate. M-tile 64 per block, 128 threads.
// ---------------------------------------------------------------------------
__device__ __forceinline__ void mma_bf16(float& d0, float& d1, float& d2, float& d3,
                                         uint32_t a0, uint32_t a1, uint32_t a2, uint32_t a3,
                                         uint32_t b0, uint32_t b1) {
    asm volatile(
        "mma.sync.aligned.m16n8k16.row.col.f32.bf16.bf16.f32 "
        "{%0,%1,%2,%3}, {%4,%5,%6,%7}, {%8,%9}, {%0,%1,%2,%3};\n"
        : "+f"(d0), "+f"(d1), "+f"(d2), "+f"(d3)
        : "r"(a0), "r"(a1), "r"(a2), "r"(a3), "r"(b0), "r"(b1));
}

__global__ __launch_bounds__(128, 8)
void emissions_gemm_kernel(const float* __restrict__ feat,
                           const float* __restrict__ Wg,
                           const float* __restrict__ bias,
                           float* __restrict__ xout) {
    // smem as 32-bit words (each word = bf16x2 pair along k)
    __shared__ uint32_t Asm[64 * 36];   // 64 rows, 32 k-pair words + pad 4
    __shared__ uint32_t Wp [32 * 40];   // 32 k-pair rows, 32 n cols + pad 8

    const int tid  = threadIdx.x;
    const int lane = tid & 31;
    const int w    = tid >> 5;          // 4 warps, 16 rows each
    const int m0   = blockIdx.x * 64;

    float acc[4][4];
#pragma unroll
    for (int i = 0; i < 4; i++)
#pragma unroll
        for (int j = 0; j < 4; j++) acc[i][j] = 0.f;

    for (int kc = 0; kc < DIM; kc += 64) {
        __syncthreads();
        // --- stage A tile: rows w*16..w*16+15, this lane covers k-pair word = lane
#pragma unroll
        for (int r = 0; r < 16; r++) {
            const int row = w * 16 + r;
            const float2 f2 = *reinterpret_cast<const float2*>(
                feat + (size_t)(m0 + row) * DIM + kc + 2 * lane);
            __nv_bfloat162 h = __floats2bfloat162_rn(f2.x, f2.y);
            Asm[row * 36 + lane] = *reinterpret_cast<uint32_t*>(&h);
        }
        // --- stage W tile: Wp[kp][n] = pack(W[kc+2kp][n], W[kc+2kp+1][n])
#pragma unroll
        for (int i = 0; i < 8; i++) {
            const int idx = tid + i * 128;  // 1024 pairs
            const int kp = idx >> 5, n = idx & 31;
            const float lo = Wg[(size_t)(kc + 2 * kp) * TAGS + n];
            const float hi = Wg[(size_t)(kc + 2 * kp + 1) * TAGS + n];
            __nv_bfloat162 h = __floats2bfloat162_rn(lo, hi);
            Wp[kp * 40 + n] = *reinterpret_cast<uint32_t*>(&h);
        }
        __syncthreads();

        const int g = lane >> 2;        // 0..7
        const int t = lane & 3;         // 0..3
#pragma unroll
        for (int kf = 0; kf < 4; kf++) {
            const int kw = 8 * kf;      // word base for this k16 fragment
            const uint32_t a0 = Asm[(w * 16 + g)     * 36 + kw + t];
            const uint32_t a1 = Asm[(w * 16 + g + 8) * 36 + kw + t];
            const uint32_t a2 = Asm[(w * 16 + g)     * 36 + kw + 4 + t];
            const uint32_t a3 = Asm[(w * 16 + g + 8) * 36 + kw + 4 + t];
#pragma unroll
            for (int nf = 0; nf < 4; nf++) {
                const uint32_t b0 = Wp[(kw + t)     * 40 + nf * 8 + g];
                const uint32_t b1 = Wp[(kw + 4 + t) * 40 + nf * 8 + g];
                mma_bf16(acc[nf][0], acc[nf][1], acc[nf][2], acc[nf][3],
                         a0, a1, a2, a3, b0, b1);
            }
        }
    }

    // epilogue: c0:(g, 2t) c1:(g, 2t+1) c2:(g+8, 2t) c3:(g+8, 2t+1)
    const int g = lane >> 2;
    const int c2 = (lane & 3) * 2;
    const int row0 = m0 + w * 16 + g;
    const int row1 = row0 + 8;
#pragma unroll
    for (int nf = 0; nf < 4; nf++) {
        const int col = nf * 8 + c2;
        const float bv0 = bias[col], bv1 = bias[col + 1];
        float2 o0 = make_float2(acc[nf][0] + bv0, acc[nf][1] + bv1);
        float2 o1 = make_float2(acc[nf][2] + bv0, acc[nf][3] + bv1);
        *reinterpret_cast<float2*>(xout + (size_t)row0 * TAGS + col) = o0;
        *reinterpret_cast<float2*>(xout + (size_t)row1 * TAGS + col) = o1;
    }
}

// ---------------------------------------------------------------------------
// Kernel 2: CRF forward recursion + numerator score. One warp per batch.
// Linear-space recursion: p' = (p @ expT) * exp(e_t), log-scale C carried,
// renormalized by p[lane 0] every 4 steps.
// ---------------------------------------------------------------------------
__device__ __forceinline__ int tag_at(const int* __restrict__ tg, int idx, bool is64) {
    return is64 ? tg[2 * idx] : tg[idx];   // little-endian low word carries value
}

__device__ __forceinline__ float dot_bcast(float p, const float* Tc) {
    float s0 = 0.f, s1 = 0.f, s2 = 0.f, s3 = 0.f;
#pragma unroll
    for (int j = 0; j < 32; j += 4) {
        s0 = fmaf(__shfl_sync(0xffffffffu, p, j),     Tc[j],     s0);
        s1 = fmaf(__shfl_sync(0xffffffffu, p, j + 1), Tc[j + 1], s1);
        s2 = fmaf(__shfl_sync(0xffffffffu, p, j + 2), Tc[j + 2], s2);
        s3 = fmaf(__shfl_sync(0xffffffffu, p, j + 3), Tc[j + 3], s3);
    }
    return (s0 + s1) + (s2 + s3);
}

__global__ void crf_scan_kernel(const int* __restrict__ tags,
                                const float* __restrict__ start_t,
                                const float* __restrict__ end_t,
                                const float* __restrict__ trans) {
    const unsigned F = 0xffffffffu;
    const int lane = threadIdx.x;
    const int b = blockIdx.x;

    // --- detect tag dtype (int64 vs int32) from odd int32 words of row 0.
    // Row 0 positions 0..128 are always valid tags (length >= 256).
    {
        // nothing; done below with ballot
    }
    const int v1 = tags[2 * lane + 1];
    const int v2 = tags[2 * lane + 65];
    const bool ok = (v1 == 0 || v1 == -1) && (v2 == 0 || v2 == -1);
    const bool is64 = __all_sync(F, ok);

    const int* tg = tags;
    const int base = b * SEQ;

    // --- length = count of non -1 tags (mask is a contiguous prefix)
    int len = 0;
#pragma unroll
    for (int k = 0; k < SEQ / 32; k++) {
        const int tv = tag_at(tg, base + k * 32 + lane, is64);
        len += __popc(__ballot_sync(F, tv != -1));
    }

    // --- constants per lane
    float Tc[32];                 // Tc[j] = exp(trans[j][lane])
#pragma unroll
    for (int j = 0; j < 32; j++) Tc[j] = __expf(trans[j * 32 + lane]);
    const float st  = start_t[lane];
    const float en  = end_t[lane];

    const float* xrow = g_x + (size_t)b * SEQ * TAGS;

    // --- init (t = 0)
    const float x0 = xrow[lane];
    float p = __expf(st + x0);
    float C = 0.f;
    int tprev = tag_at(tg, base + 0, is64);
    float score = __shfl_sync(F, st, tprev) + __shfl_sync(F, x0, tprev);

    // --- prefetch t = 1..4
    float e0 = 0.f, e1 = 0.f, e2 = 0.f, e3 = 0.f;
    int   g0 = 0,   g1 = 0,   g2 = 0,   g3 = 0;
    if (1 < len) { e0 = xrow[1 * 32 + lane]; g0 = tag_at(tg, base + 1, is64); }
    if (2 < len) { e1 = xrow[2 * 32 + lane]; g1 = tag_at(tg, base + 2, is64); }
    if (3 < len) { e2 = xrow[3 * 32 + lane]; g2 = tag_at(tg, base + 3, is64); }
    if (4 < len) { e3 = xrow[4 * 32 + lane]; g3 = tag_at(tg, base + 4, is64); }

    int t = 1;
#define CRF_STEP(E, G)                                                        \
    {                                                                         \
        const float ee = __expf(E);                                           \
        const int tc = G;                                                     \
        score += __shfl_sync(F, E, tc) + trans[tprev * 32 + tc];              \
        tprev = tc;                                                           \
        const float s = dot_bcast(p, Tc);                                     \
        p = s * ee;                                                           \
        const int tn = t + 4;                                                 \
        const bool okn = tn < len;                                            \
        E = okn ? xrow[tn * 32 + lane] : 0.f;                                 \
        G = okn ? tag_at(tg, base + tn, is64) : 0;                            \
        t++;                                                                  \
    }

    while (t < len) {
        CRF_STEP(e0, g0); if (t >= len) break;
        CRF_STEP(e1, g1); if (t >= len) break;
        CRF_STEP(e2, g2); if (t >= len) break;
        CRF_STEP(e3, g3);
        // renormalize every 4 steps: divide by p[0], log goes into C
        const float m = __shfl_sync(F, p, 0);
        float inv;
        asm("rcp.approx.f32 %0, %1;" : "=f"(inv) : "f"(m));
        p *= inv;
        C += __logf(m);
    }
#undef CRF_STEP

    // --- finish: log_z = C + log( sum_j p_j * exp(end_j) )
    float v = p * __expf(en);
#pragma unroll
    for (int off = 16; off > 0; off >>= 1) v += __shfl_xor_sync(F, v, off);
    const float log_z = C + __logf(v);

    score += __shfl_sync(F, en, tprev);   // end_transitions[last_tag]

    if (lane == 0) g_llh[b] = score - log_z;
}

// ---------------------------------------------------------------------------
// Kernel 3: out = -mean(llh)
// ---------------------------------------------------------------------------
__global__ void finish_kernel(float* __restrict__ out) {
    const int lane = threadIdx.x;
    float v = g_llh[lane] + g_llh[lane + 32];
#pragma unroll
    for (int off = 16; off > 0; off >>= 1) v += __shfl_xor_sync(0xffffffffu, v, off);
    if (lane == 0) out[0] = -v * (1.0f / (float)BATCH);
}

// ---------------------------------------------------------------------------
extern "C" void kernel_launch(void* const* d_in, const int* in_sizes, int n_in,
                              void* d_out, int out_size) {
    const float* feat    = (const float*)d_in[0];   // (64,512,1024) fp32
    const int*   tags    = (const int*)  d_in[1];   // (64,512) int32 or int64 (detected)
    const float* W       = (const float*)d_in[2];   // (1024,32)
    const float* bias    = (const float*)d_in[3];   // (32,)
    const float* start_t = (const float*)d_in[4];   // (32,)
    const float* end_t   = (const float*)d_in[5];   // (32,)
    const float* trans   = (const float*)d_in[6];   // (32,32)
    float* out = (float*)d_out;

    float* xg = nullptr;
    cudaGetSymbolAddress((void**)&xg, g_x);

    emissions_gemm_kernel<<<(BATCH * SEQ) / 64, 128>>>(feat, W, bias, xg);
    crf_scan_kernel<<<BATCH, 32>>>(tags, start_t, end_t, trans);
    finish_kernel<<<1, 32>>>(out);
}

// round 2
// speedup vs baseline: 1.4483x; 1.4483x over previous
#include <cuda_runtime.h>
#include <cuda_bf16.h>
#include <cstdint>

#define BATCH 64
#define SEQ   512
#define DIM   1024
#define TAGS  32

__device__ float g_x[BATCH * SEQ * TAGS];
__device__ float g_llh[BATCH];

// ---------------------------------------------------------------------------
// Kernel 1: emissions GEMM.  x[32768,32] = feat[32768,1024] @ W[1024,32] + b
// bf16 mma.sync m16n8k16, fp32 accumulate.
// 256 threads/block, M-tile 64, K-chunk 128, register double-buffering.
// ---------------------------------------------------------------------------
__device__ __forceinline__ void mma_bf16(float& d0, float& d1, float& d2, float& d3,
                                         uint32_t a0, uint32_t a1, uint32_t a2, uint32_t a3,
                                         uint32_t b0, uint32_t b1) {
    asm volatile(
        "mma.sync.aligned.m16n8k16.row.col.f32.bf16.bf16.f32 "
        "{%0,%1,%2,%3}, {%4,%5,%6,%7}, {%8,%9}, {%0,%1,%2,%3};\n"
        : "+f"(d0), "+f"(d1), "+f"(d2), "+f"(d3)
        : "r"(a0), "r"(a1), "r"(a2), "r"(a3), "r"(b0), "r"(b1));
}

__device__ __forceinline__ uint32_t pack_bf16(float lo, float hi) {
    __nv_bfloat162 h = __floats2bfloat162_rn(lo, hi);
    return *reinterpret_cast<uint32_t*>(&h);
}

#define ASTRIDE 68   // 68 mod 32 = 4 -> mma A-reads conflict-free
#define WSTRIDE 40   // 40 mod 32 = 8 -> mma B-reads conflict-free

__global__ __launch_bounds__(256)
void emissions_gemm_kernel(const float* __restrict__ feat,
                           const float* __restrict__ Wg,
                           const float* __restrict__ bias,
                           float* __restrict__ xout) {
    __shared__ uint32_t Asm[64 * ASTRIDE];  // 64 rows x 64 k-pair words
    __shared__ uint32_t Wp [64 * WSTRIDE];  // 64 k-pair rows x 32 n

    const int tid  = threadIdx.x;
    const int lane = tid & 31;
    const int w    = tid >> 5;              // 8 warps
    const int m0   = blockIdx.x * 64;

    float4 areg[8];
    float  wlo[8], whi[8];

    const int arow = tid >> 5;              // reuse mapping helpers below
    (void)arow;

    // --- preload chunk 0 into registers
#pragma unroll
    for (int i = 0; i < 8; i++) {
        const int idx = tid + i * 256;      // 2048 float4s = 64 rows x 32
        const int row = idx >> 5, kq = idx & 31;
        areg[i] = *reinterpret_cast<const float4*>(
            feat + (size_t)(m0 + row) * DIM + 4 * kq);
    }
#pragma unroll
    for (int i = 0; i < 8; i++) {
        const int idx = tid + i * 256;      // 2048 words = 64 kp x 32 n
        const int kp = idx >> 5, n = idx & 31;
        wlo[i] = Wg[(size_t)(2 * kp) * TAGS + n];
        whi[i] = Wg[(size_t)(2 * kp + 1) * TAGS + n];
    }

    float acc[2][4];
#pragma unroll
    for (int f = 0; f < 2; f++)
#pragma unroll
        for (int j = 0; j < 4; j++) acc[f][j] = 0.f;

    const int rb = (w & 3) * 16;
    const int nb = (w >> 2) * 16;
    const int g  = lane >> 2;
    const int t  = lane & 3;

    for (int c = 0; c < 8; c++) {
        // --- store staged registers to smem
#pragma unroll
        for (int i = 0; i < 8; i++) {
            const int idx = tid + i * 256;
            const int row = idx >> 5, kq = idx & 31;
            Asm[row * ASTRIDE + 2 * kq]     = pack_bf16(areg[i].x, areg[i].y);
            Asm[row * ASTRIDE + 2 * kq + 1] = pack_bf16(areg[i].z, areg[i].w);
        }
#pragma unroll
        for (int i = 0; i < 8; i++) {
            const int idx = tid + i * 256;
            const int kp = idx >> 5, n = idx & 31;
            Wp[kp * WSTRIDE + n] = pack_bf16(wlo[i], whi[i]);
        }
        __syncthreads();

        // --- issue next chunk's loads (overlap with mma below)
        if (c < 7) {
            const int kc = (c + 1) * 128;
#pragma unroll
            for (int i = 0; i < 8; i++) {
                const int idx = tid + i * 256;
                const int row = idx >> 5, kq = idx & 31;
                areg[i] = *reinterpret_cast<const float4*>(
                    feat + (size_t)(m0 + row) * DIM + kc + 4 * kq);
            }
#pragma unroll
            for (int i = 0; i < 8; i++) {
                const int idx = tid + i * 256;
                const int kp = idx >> 5, n = idx & 31;
                wlo[i] = Wg[(size_t)(kc + 2 * kp) * TAGS + n];
                whi[i] = Wg[(size_t)(kc + 2 * kp + 1) * TAGS + n];
            }
        }

        // --- mma over the 128-k chunk (8 x k16 fragments)
#pragma unroll
        for (int kf = 0; kf < 8; kf++) {
            const int kw = 8 * kf;
            const uint32_t a0 = Asm[(rb + g)     * ASTRIDE + kw + t];
            const uint32_t a1 = Asm[(rb + g + 8) * ASTRIDE + kw + t];
            const uint32_t a2 = Asm[(rb + g)     * ASTRIDE + kw + 4 + t];
            const uint32_t a3 = Asm[(rb + g + 8) * ASTRIDE + kw + 4 + t];
#pragma unroll
            for (int f = 0; f < 2; f++) {
                const uint32_t b0 = Wp[(kw + t)     * WSTRIDE + nb + 8 * f + g];
                const uint32_t b1 = Wp[(kw + 4 + t) * WSTRIDE + nb + 8 * f + g];
                mma_bf16(acc[f][0], acc[f][1], acc[f][2], acc[f][3],
                         a0, a1, a2, a3, b0, b1);
            }
        }
        __syncthreads();
    }

    // epilogue: acc[f]{0,1}->(row g, cols nb+8f+2t,+1) ; {2,3}->(row g+8)
    const int c2 = 2 * t;
    const int row0 = m0 + rb + g;
#pragma unroll
    for (int f = 0; f < 2; f++) {
        const int col = nb + 8 * f + c2;
        const float bv0 = bias[col], bv1 = bias[col + 1];
        *reinterpret_cast<float2*>(xout + (size_t)row0 * TAGS + col) =
            make_float2(acc[f][0] + bv0, acc[f][1] + bv1);
        *reinterpret_cast<float2*>(xout + (size_t)(row0 + 8) * TAGS + col) =
            make_float2(acc[f][2] + bv0, acc[f][3] + bv1);
    }
}

// ---------------------------------------------------------------------------
// Kernel 2: CRF forward recursion + numerator. One warp per batch.
// Branch-free fixed 512-step loop, 8-deep prefetch, renorm every 4 steps.
// ---------------------------------------------------------------------------
__device__ __forceinline__ int tag_at(const int* __restrict__ tg, int idx, bool is64) {
    return is64 ? __ldg(tg + 2 * idx) : __ldg(tg + idx);
}

__device__ __forceinline__ float dot_bcast(float p, const float* Tc) {
    const unsigned F = 0xffffffffu;
    float s0 = 0.f, s1 = 0.f, s2 = 0.f, s3 = 0.f;
#pragma unroll
    for (int j = 0; j < 32; j += 4) {
        s0 = fmaf(__shfl_sync(F, p, j),     Tc[j],     s0);
        s1 = fmaf(__shfl_sync(F, p, j + 1), Tc[j + 1], s1);
        s2 = fmaf(__shfl_sync(F, p, j + 2), Tc[j + 2], s2);
        s3 = fmaf(__shfl_sync(F, p, j + 3), Tc[j + 3], s3);
    }
    return (s0 + s1) + (s2 + s3);
}

__global__ void crf_scan_kernel(const int* __restrict__ tags,
                                const float* __restrict__ start_t,
                                const float* __restrict__ end_t,
                                const float* __restrict__ trans) {
    const unsigned F = 0xffffffffu;
    const int lane = threadIdx.x;
    const int b = blockIdx.x;

    // detect int64 vs int32 tag layout (odd words all in {0,-1} <=> int64)
    const int v1 = tags[2 * lane + 1];
    const int v2 = tags[2 * lane + 65];
    const bool ok = (v1 == 0 || v1 == -1) && (v2 == 0 || v2 == -1);
    const bool is64 = __all_sync(F, ok);

    const int* tg = tags;
    const int base = b * SEQ;

    // length = popcount of valid prefix
    int len = 0;
#pragma unroll
    for (int k = 0; k < SEQ / 32; k++) {
        const int tv = tag_at(tg, base + k * 32 + lane, is64);
        len += __popc(__ballot_sync(F, tv != -1));
    }

    float Tc[32];
#pragma unroll
    for (int j = 0; j < 32; j++) Tc[j] = __expf(__ldg(trans + j * 32 + lane));
    const float st = __ldg(start_t + lane);
    const float en = __ldg(end_t + lane);

    const float* xrow = g_x + (size_t)b * SEQ * TAGS;

    // t = 0
    const float x0 = __ldg(xrow + lane);
    float p = __expf(st + x0);
    float C = 0.f;
    int tprev = tag_at(tg, base, is64);
    float score = __shfl_sync(F, st, tprev) + __shfl_sync(F, x0, tprev);

    // prefetch t = 1..8
    float E[8];
    int   G[8];
#pragma unroll
    for (int i = 0; i < 8; i++) {
        const int tt = 1 + i;
        const bool okp = tt < len;
        E[i] = okp ? __ldg(xrow + tt * 32 + lane) : 0.f;
        G[i] = okp ? tag_at(tg, base + tt, is64) : 0;
    }

    // 64 groups x 8 steps = t in [1, 512]; steps with t >= len are masked.
    for (int grp = 0; grp < 64; grp++) {
#pragma unroll
        for (int i = 0; i < 8; i++) {
            const int tt = 1 + grp * 8 + i;
            const bool valid = tt < len;

            const float ee = __expf(E[i]);
            const int tc = G[i];
            const float contrib =
                __shfl_sync(F, E[i], tc) + __ldg(trans + tprev * 32 + tc);
            if (valid) { score += contrib; tprev = tc; }

            const float s = dot_bcast(p, Tc);
            p = valid ? s * ee : p;

            const int tn = tt + 8;
            const bool okn = tn < len;
            E[i] = okn ? __ldg(xrow + tn * 32 + lane) : 0.f;
            G[i] = okn ? tag_at(tg, base + tn, is64) : 0;

            if ((i & 3) == 3) {
                const float m = __shfl_sync(F, p, 0);
                float inv;
                asm("rcp.approx.f32 %0, %1;" : "=f"(inv) : "f"(m));
                p *= inv;
                C += __logf(m);
            }
        }
    }

    // log_z = C + log(sum_j p_j * exp(end_j))
    float v = p * __expf(en);
#pragma unroll
    for (int off = 16; off > 0; off >>= 1) v += __shfl_xor_sync(F, v, off);
    const float log_z = C + __logf(v);

    score += __shfl_sync(F, en, tprev);

    if (lane == 0) g_llh[b] = score - log_z;
}

// ---------------------------------------------------------------------------
// Kernel 3: out = -mean(llh)
// ---------------------------------------------------------------------------
__global__ void finish_kernel(float* __restrict__ out) {
    const int lane = threadIdx.x;
    float v = g_llh[lane] + g_llh[lane + 32];
#pragma unroll
    for (int off = 16; off > 0; off >>= 1) v += __shfl_xor_sync(0xffffffffu, v, off);
    if (lane == 0) out[0] = -v * (1.0f / (float)BATCH);
}

// ---------------------------------------------------------------------------
extern "C" void kernel_launch(void* const* d_in, const int* in_sizes, int n_in,
                              void* d_out, int out_size) {
    const float* feat    = (const float*)d_in[0];
    const int*   tags    = (const int*)  d_in[1];
    const float* W       = (const float*)d_in[2];
    const float* bias    = (const float*)d_in[3];
    const float* start_t = (const float*)d_in[4];
    const float* end_t   = (const float*)d_in[5];
    const float* trans   = (const float*)d_in[6];
    float* out = (float*)d_out;

    float* xg = nullptr;
    cudaGetSymbolAddress((void**)&xg, g_x);

    emissions_gemm_kernel<<<(BATCH * SEQ) / 64, 256>>>(feat, W, bias, xg);
    crf_scan_kernel<<<BATCH, 32>>>(tags, start_t, end_t, trans);
    finish_kernel<<<1, 32>>>(out);
}